// round 15
// baseline (speedup 1.0000x reference)
#include <cuda_runtime.h>
#include <cstddef>

// Problem constants
#define T_STEPS   1024
#define CHUNK     64
#define NCHUNK    (T_STEPS / CHUNK)   // 16
#define HDIM      64
#define NSEQ      2                    // sequences per 64-thread group
#define GROUPS    2                    // groups per CTA
#define NCS       (NSEQ * GROUPS)      // sequences per CTA = 4
#define THREADS   (64 * GROUPS)        // 128
#define BTOT      4096
#define GRID1     (BTOT / 2)           // 2048: CTA b owns batch elems {2b, 2b+1}

#define LOG2E  1.4426950408889634f
#define LOG2E2 2.8853900817779268f

// ---- packed f32x2 helpers (FFMA2: 2 fp32 FMAs per issue) ----
__device__ __forceinline__ unsigned long long pk2(float lo, float hi) {
    unsigned long long r;
    asm("mov.b64 %0, {%1, %2};" : "=l"(r) : "f"(lo), "f"(hi));
    return r;
}
__device__ __forceinline__ unsigned long long ffma2(unsigned long long a,
                                                    unsigned long long b,
                                                    unsigned long long c) {
    unsigned long long d;
    asm("fma.rn.f32x2 %0, %1, %2, %3;" : "=l"(d) : "l"(a), "l"(b), "l"(c));
    return d;
}
__device__ __forceinline__ float hsum2(unsigned long long v) {
    float lo, hi;
    asm("mov.b64 {%0, %1}, %2;" : "=f"(lo), "=f"(hi) : "l"(v));
    return lo + hi;
}
// raw MUFU.EX2 (same accuracy class as __expf's internal EX2)
__device__ __forceinline__ float ex2a(float x) {
    float r;
    asm("ex2.approx.f32 %0, %1;" : "=f"(r) : "f"(x));
    return r;
}

// activations on PRESCALED pre-activations:
//  y_r already multiplied by log2e  -> sigma = 1/(1+2^-y)
//  y_n already multiplied by 2log2e -> tanh  = 2/(1+2^-y) - 1
__device__ __forceinline__ float sigm_p(float y) {
    return __fdividef(1.0f, 1.0f + ex2a(-y));
}
__device__ __forceinline__ float tanh_p(float y) {
    return __fdividef(2.0f, 1.0f + ex2a(-y)) - 1.0f;
}
// exact sigmoid for the head (unscaled input)
__device__ __forceinline__ float sigm(float x) {
    return __fdividef(1.0f, 1.0f + ex2a(-x * LOG2E));
}

// ============================================================================
// Fused Siamese-GRU kernel. CTA b handles batch elems {2b, 2b+1}:
//   seq q=0,1 : x1 rows 2b, 2b+1    seq q=2,3 : x2 rows 2b, 2b+1
// 64-thread group g advances seqs {2g, 2g+1}; thread u owns W_hh rows
// {u, u+64} (r,z gates) register-resident f32x2-packed; the n-gate row
// lives in SMEM ([k][u] layout, conflict-free LDS.128) and is re-read per k,
// shared across the 2 seqs -> frees 64 regs vs all-register (kills spills).
// All gate weights prescaled by log2e (r,z) / 2log2e (n) so activations use
// raw ex2.approx with no scaling FMUL. h double-buffered in SMEM; one
// __syncthreads per timestep. Head fused in-CTA at the end.
// ============================================================================
__global__ void __launch_bounds__(THREADS, 2)
siamese_gru_kernel(const float* __restrict__ x1, const float* __restrict__ x2,
                   const float* __restrict__ Wih, const float* __restrict__ Whh,
                   const float* __restrict__ bih, const float* __restrict__ bhh,
                   const float* __restrict__ W1, const float* __restrict__ b1,
                   const float* __restrict__ W2, const float* __restrict__ b2,
                   float* __restrict__ out)
{
    __shared__ __align__(16) float h_sh[2][NCS][HDIM];        // 2 KB
    __shared__ __align__(16) float x_sh[NCS][CHUNK * 3];      // 3 KB
    __shared__ __align__(16) ulonglong2 wn_sh[16][HDIM];      // 16 KB, n-gate W
    __shared__ float d_sh[2][HDIM];                           // head scratch

    const int tid = threadIdx.x;
    const int u   = tid & 63;     // hidden unit owned by this thread
    const int grp = tid >> 6;     // group within CTA

    // ---- r,z recurrent weights register-resident, prescaled by log2e ----
    unsigned long long wr[32], wz[32];
#pragma unroll
    for (int i = 0; i < 32; i++) {
        wr[i] = pk2(LOG2E * Whh[(u     ) * 64 + 2 * i], LOG2E * Whh[(u     ) * 64 + 2 * i + 1]);
        wz[i] = pk2(LOG2E * Whh[(u + 64) * 64 + 2 * i], LOG2E * Whh[(u + 64) * 64 + 2 * i + 1]);
    }
    // ---- n-gate recurrent weights -> SMEM, prescaled by 2log2e ----
    if (grp == 0) {
#pragma unroll
        for (int i = 0; i < 16; i++) {
            const float* p = Whh + (u + 128) * 64 + 4 * i;
            ulonglong2 v;
            v.x = pk2(LOG2E2 * p[0], LOG2E2 * p[1]);
            v.y = pk2(LOG2E2 * p[2], LOG2E2 * p[3]);
            wn_sh[i][u] = v;
        }
    }

    // input-side weights (D = 3), prescaled
    const float wir0 = LOG2E  * Wih[(u      ) * 3 + 0], wir1 = LOG2E  * Wih[(u      ) * 3 + 1], wir2 = LOG2E  * Wih[(u      ) * 3 + 2];
    const float wiz0 = LOG2E  * Wih[(u +  64) * 3 + 0], wiz1 = LOG2E  * Wih[(u +  64) * 3 + 1], wiz2 = LOG2E  * Wih[(u +  64) * 3 + 2];
    const float win0 = LOG2E2 * Wih[(u + 128) * 3 + 0], win1 = LOG2E2 * Wih[(u + 128) * 3 + 1], win2 = LOG2E2 * Wih[(u + 128) * 3 + 2];
    // biases (prescaled). n keeps b_ih / b_hh split: n = tanh(xn + r*(dn + bhn))
    const float cr  = LOG2E  * (bih[u]      + bhh[u]);
    const float cz  = LOG2E  * (bih[u + 64] + bhh[u + 64]);
    const float cxn = LOG2E2 * bih[u + 128];
    const float bhn = LOG2E2 * bhh[u + 128];

    float hreg[NSEQ];
#pragma unroll
    for (int s = 0; s < NSEQ; s++) {
        hreg[s] = 0.0f;
        h_sh[0][grp * NSEQ + s][u] = 0.0f;
    }
    __syncthreads();

    int buf = 0;
    for (int tc = 0; tc < NCHUNK; tc++) {
        // ---- stage x chunk: NCS seqs x CHUNK steps x 3 floats, float4 coalesced ----
        for (int i = tid; i < NCS * (CHUNK * 3 / 4); i += THREADS) {
            const int q = i / 48;
            const int j = i - q * 48;
            const float* base = (q < 2)
                ? (x1 + (size_t)(2 * blockIdx.x + q)     * (T_STEPS * 3))
                : (x2 + (size_t)(2 * blockIdx.x + q - 2) * (T_STEPS * 3));
            reinterpret_cast<float4*>(&x_sh[q][0])[j] =
                reinterpret_cast<const float4*>(base + tc * (CHUNK * 3))[j];
        }
        __syncthreads();

        for (int tl = 0; tl < CHUNK; tl++) {
            const int q0 = grp * NSEQ;
            const ulonglong2* hp0 =
                reinterpret_cast<const ulonglong2*>(&h_sh[buf][q0][0]);
            const ulonglong2* hp1 =
                reinterpret_cast<const ulonglong2*>(&h_sh[buf][q0 + 1][0]);

            unsigned long long ar0 = 0ull, az0 = 0ull, an0 = 0ull;
            unsigned long long ar1 = 0ull, az1 = 0ull, an1 = 0ull;
#pragma unroll
            for (int k = 0; k < 16; k++) {
                const ulonglong2 wnk = wn_sh[k][u];   // conflict-free LDS.128
                const ulonglong2 h40 = hp0[k];        // broadcast LDS.128
                const ulonglong2 h41 = hp1[k];
                ar0 = ffma2(wr[2 * k],     h40.x, ar0);
                az0 = ffma2(wz[2 * k],     h40.x, az0);
                an0 = ffma2(wnk.x,         h40.x, an0);
                ar0 = ffma2(wr[2 * k + 1], h40.y, ar0);
                az0 = ffma2(wz[2 * k + 1], h40.y, az0);
                an0 = ffma2(wnk.y,         h40.y, an0);
                ar1 = ffma2(wr[2 * k],     h41.x, ar1);
                az1 = ffma2(wz[2 * k],     h41.x, az1);
                an1 = ffma2(wnk.x,         h41.x, an1);
                ar1 = ffma2(wr[2 * k + 1], h41.y, ar1);
                az1 = ffma2(wz[2 * k + 1], h41.y, az1);
                an1 = ffma2(wnk.y,         h41.y, an1);
            }

#pragma unroll
            for (int s = 0; s < NSEQ; s++) {
                const int q = q0 + s;
                const float xv0 = x_sh[q][tl * 3 + 0];
                const float xv1 = x_sh[q][tl * 3 + 1];
                const float xv2 = x_sh[q][tl * 3 + 2];
                const float xr = fmaf(xv2, wir2, fmaf(xv1, wir1, fmaf(xv0, wir0, cr)));
                const float xz = fmaf(xv2, wiz2, fmaf(xv1, wiz1, fmaf(xv0, wiz0, cz)));
                const float xn = fmaf(xv2, win2, fmaf(xv1, win1, fmaf(xv0, win0, cxn)));

                const float dr = hsum2(s == 0 ? ar0 : ar1);
                const float dz = hsum2(s == 0 ? az0 : az1);
                const float dn = hsum2(s == 0 ? an0 : an1);

                const float r = sigm_p(xr + dr);
                const float z = sigm_p(xz + dz);
                const float n = tanh_p(xn + r * (dn + bhn));
                const float hnew = n + z * (hreg[s] - n);   // (1-z)n + z h
                hreg[s] = hnew;
                h_sh[buf ^ 1][q][u] = hnew;
            }
            buf ^= 1;
            __syncthreads();   // new h visible; old buffer free for next step
        }
    }

    // ========================================================================
    // In-CTA head: diff -> Linear(64,32) -> ReLU -> Linear(32,1) -> Sigmoid.
    // ========================================================================
    {
        const int e = grp;   // 128 threads cover (elem, unit) = (tid>>6, tid&63)
        d_sh[e][u] = fabsf(h_sh[buf][e][u] - h_sh[buf][2 + e][u]);
    }
    __syncthreads();

    if (tid < 64) {
        const int w = tid >> 5;   // batch elem (warp 0 -> 2b, warp 1 -> 2b+1)
        const int r = tid & 31;   // hidden-unit of the 32-wide MLP layer
        const float* w1r = W1 + r * 64;
        float acc = b1[r];
#pragma unroll 8
        for (int k = 0; k < 64; k++)
            acc = fmaf(d_sh[w][k], w1r[k], acc);
        const float hid = fmaxf(acc, 0.0f);
        float p = hid * W2[r];
#pragma unroll
        for (int off = 16; off; off >>= 1)
            p += __shfl_xor_sync(0xffffffffu, p, off);
        if (r == 0)
            out[2 * blockIdx.x + w] = sigm(p + b2[0]);
    }
}

// ============================================================================
// Launch (graph-capturable: single kernel launch, no allocs/syncs)
// Input order (metadata): x1, x2, W_ih, W_hh, b_ih, b_hh, W1, b1, W2, b2
// ============================================================================
extern "C" void kernel_launch(void* const* d_in, const int* in_sizes, int n_in,
                              void* d_out, int out_size)
{
    (void)in_sizes; (void)n_in; (void)out_size;
    const float* x1  = (const float*)d_in[0];
    const float* x2  = (const float*)d_in[1];
    const float* Wih = (const float*)d_in[2];
    const float* Whh = (const float*)d_in[3];
    const float* bih = (const float*)d_in[4];
    const float* bhh = (const float*)d_in[5];
    const float* W1  = (const float*)d_in[6];
    const float* b1  = (const float*)d_in[7];
    const float* W2  = (const float*)d_in[8];
    const float* b2  = (const float*)d_in[9];
    float* out = (float*)d_out;

    siamese_gru_kernel<<<GRID1, THREADS>>>(x1, x2, Wih, Whh, bih, bhh,
                                           W1, b1, W2, b2, out);
}